// round 2
// baseline (speedup 1.0000x reference)
#include <cuda_runtime.h>
#include <math.h>
#include <float.h>

#define NQ   512
#define NC   16
#define CS   64
#define HID  128
#define NB   2048
#define MST  20   // padded row stride (floats) for s_mT: 16B-aligned, 4-way-conflict writes only

__device__ float g_Wt[HID * HID];     // g_Wt[h*128 + o] = W[o*128 + h]
__device__ float g_anorm[NC * NC];

typedef unsigned long long u64;

static __device__ __forceinline__ u64 pack2(float lo, float hi) {
    u64 r; asm("mov.b64 %0, {%1, %2};" : "=l"(r) : "f"(lo), "f"(hi)); return r;
}
static __device__ __forceinline__ void ffma2(u64 &d, u64 a, u64 b) {
    asm("fma.rn.f32x2 %0, %1, %2, %0;" : "+l"(d) : "l"(a), "l"(b));
}
static __device__ __forceinline__ float2 unpack2(u64 v) {
    float x, y; asm("mov.b64 {%0, %1}, %2;" : "=f"(x), "=f"(y) : "l"(v));
    return make_float2(x, y);
}
static __device__ __forceinline__ float4 max4(float4 a, float4 b) {
    return make_float4(fmaxf(a.x, b.x), fmaxf(a.y, b.y), fmaxf(a.z, b.z), fmaxf(a.w, b.w));
}

// ---------------- prep: transpose W, build normalized adjacency ----------------
__global__ void prep_kernel(const float* __restrict__ adj, const float* __restrict__ W) {
    int t = threadIdx.x;
    if (blockIdx.x < 64) {
        int idx = blockIdx.x * 256 + t;      // 0..16383
        int o = idx >> 7, h = idx & 127;
        g_Wt[h * HID + o] = W[idx];          // W[o][h] -> Wt[h][o]
    } else {
        int i = t >> 4, j = t & 15;
        float di = 0.f, dj = 0.f;
#pragma unroll
        for (int r = 0; r < NC; r++) { di += adj[r * NC + i]; dj += adj[r * NC + j]; }
        di = di > 0.f ? rsqrtf(di) : 0.f;
        dj = dj > 0.f ? rsqrtf(dj) : 0.f;
        g_anorm[t] = adj[t] * di * dj;
    }
}

// ---------------- fused: bucket -> maxpool -> adj-mix -> GEMM ----------------
__global__ void __launch_bounds__(128)
enc_kernel(const int*   __restrict__ la,
           const float* __restrict__ qemb,
           const float* __restrict__ bias,
           float*       __restrict__ out)
{
    __shared__ int            s_assign[NQ];
    __shared__ unsigned short s_buf[NC * CS];
    __shared__ int            s_cnt[NC];
    __shared__ int            s_ovf;
    __shared__ float          s_anorm[NC * NC];
    __shared__ __align__(16) float s_ce[NC * HID];    // [core][h]
    __shared__ __align__(16) float s_mT[HID * MST];   // [h][i], padded

    const int tid  = threadIdx.x;
    const int lane = tid & 31;
    const int wrp  = tid >> 5;
    const int b    = blockIdx.x;

    if (tid < NC) s_cnt[tid] = 0;
    if (tid == NC) s_ovf = 0;
    s_anorm[tid]       = g_anorm[tid];
    s_anorm[tid + 128] = g_anorm[tid + 128];

    // load assignment row (512 ints) as int4
    int4 aa = ((const int4*)(la + (size_t)b * NQ))[tid];
    ((int4*)s_assign)[tid] = aa;
    __syncthreads();

    // ---- phase 1: bucket qubits by core (order-free; max is exact-commutative) ----
    {
        int q0 = tid * 4;
        int c, p;
        c = aa.x; p = atomicAdd(&s_cnt[c], 1); if (p < CS) s_buf[c * CS + p] = (unsigned short)(q0 + 0); else s_ovf = 1;
        c = aa.y; p = atomicAdd(&s_cnt[c], 1); if (p < CS) s_buf[c * CS + p] = (unsigned short)(q0 + 1); else s_ovf = 1;
        c = aa.z; p = atomicAdd(&s_cnt[c], 1); if (p < CS) s_buf[c * CS + p] = (unsigned short)(q0 + 2); else s_ovf = 1;
        c = aa.w; p = atomicAdd(&s_cnt[c], 1); if (p < CS) s_buf[c * CS + p] = (unsigned short)(q0 + 3); else s_ovf = 1;
    }
    __syncthreads();

    if (s_ovf) {   // rare: count>64 -> drops are order-dependent; redo serially in order
        if (tid == 0) {
            int cnt[NC];
#pragma unroll
            for (int c = 0; c < NC; c++) cnt[c] = 0;
            for (int q = 0; q < NQ; q++) {
                int c = s_assign[q];
                int p = cnt[c];
                if (p < CS) s_buf[c * CS + p] = (unsigned short)q;
                cnt[c] = p + 1;
            }
#pragma unroll
            for (int c = 0; c < NC; c++) s_cnt[c] = cnt[c];
        }
        __syncthreads();
    }

    // ---- phase 2: per-core max-pool. warp w owns cores 4w..4w+3 ----
    {
        const float4* qe4 = (const float4*)qemb;
#pragma unroll
        for (int cc = 0; cc < 4; cc++) {
            int c   = wrp * 4 + cc;
            int cnt = s_cnt[c];
            int n   = cnt < CS ? cnt : CS;
            float init = (cnt >= CS) ? -FLT_MAX : 0.0f;   // padding rows are zero
            float4 acc = make_float4(init, init, init, init);
            int i = 0;
            for (; i + 4 <= n; i += 4) {
                int q0 = s_buf[c * CS + i + 0];
                int q1 = s_buf[c * CS + i + 1];
                int q2 = s_buf[c * CS + i + 2];
                int q3 = s_buf[c * CS + i + 3];
                float4 v0 = qe4[q0 * 32 + lane];
                float4 v1 = qe4[q1 * 32 + lane];
                float4 v2 = qe4[q2 * 32 + lane];
                float4 v3 = qe4[q3 * 32 + lane];
                acc = max4(acc, v0); acc = max4(acc, v1);
                acc = max4(acc, v2); acc = max4(acc, v3);
            }
            for (; i < n; i++) {
                int q = s_buf[c * CS + i];
                acc = max4(acc, qe4[q * 32 + lane]);
            }
            ((float4*)(s_ce + c * HID))[lane] = acc;
        }
    }
    __syncthreads();

    // ---- phase 3: adjacency mix  m[i][h] = sum_j anorm[i][j] * ce[j][h] ----
    {
        float cev[NC];
#pragma unroll
        for (int j = 0; j < NC; j++) cev[j] = s_ce[j * HID + tid];
#pragma unroll
        for (int i = 0; i < NC; i++) {
            float m = 0.f;
#pragma unroll
            for (int j = 0; j < NC; j++) m = fmaf(s_anorm[i * NC + j], cev[j], m);
            s_mT[tid * MST + i] = m;   // transposed: [h][i]
        }
    }
    __syncthreads();

    // ---- phase 4: GEMM  out[b,i,o] = sum_h m[i][h]*Wt[h][o] + bias[o]; thread owns o=tid ----
    {
        u64 acc[8];
#pragma unroll
        for (int k = 0; k < 8; k++) acc[k] = 0ull;

        const float* wcol = g_Wt + tid;
#pragma unroll 8
        for (int h = 0; h < HID; h++) {
            float w = wcol[h * HID];
            u64 wp = pack2(w, w);
            const ulonglong2* mrow = (const ulonglong2*)(s_mT + h * MST);
            ulonglong2 p0 = mrow[0];   // i = 0..3
            ulonglong2 p1 = mrow[1];   // i = 4..7
            ulonglong2 p2 = mrow[2];   // i = 8..11
            ulonglong2 p3 = mrow[3];   // i = 12..15
            ffma2(acc[0], p0.x, wp); ffma2(acc[1], p0.y, wp);
            ffma2(acc[2], p1.x, wp); ffma2(acc[3], p1.y, wp);
            ffma2(acc[4], p2.x, wp); ffma2(acc[5], p2.y, wp);
            ffma2(acc[6], p3.x, wp); ffma2(acc[7], p3.y, wp);
        }

        float bo = bias[tid];
        float* ob = out + (size_t)b * (NC * HID) + tid;
#pragma unroll
        for (int k = 0; k < 8; k++) {
            float2 r = unpack2(acc[k]);
            ob[(2 * k)     * HID] = r.x + bo;
            ob[(2 * k + 1) * HID] = r.y + bo;
        }
    }
}

extern "C" void kernel_launch(void* const* d_in, const int* in_sizes, int n_in,
                              void* d_out, int out_size) {
    const int*   la   = (const int*)  d_in[0];   // (2048, 512) int32
    const float* adj  = (const float*)d_in[1];   // (16, 16) f32
    const float* qemb = (const float*)d_in[2];   // (513, 128) f32
    const float* W    = (const float*)d_in[3];   // (128, 128) f32
    const float* bias = (const float*)d_in[4];   // (128,) f32
    float* out = (float*)d_out;                  // (2048, 16, 128) f32

    prep_kernel<<<65, 256>>>(adj, W);
    enc_kernel<<<NB, 128>>>(la, qemb, bias, out);
}

// round 3
// speedup vs baseline: 1.3696x; 1.3696x over previous
#include <cuda_runtime.h>
#include <cuda_fp16.h>
#include <math.h>

#define NQ   512
#define NC   16
#define CS   64
#define HID  128
#define NB   2048
#define CTS  20   // ceT row stride (floats): 16B-aligned rows, 16 data + 4 pad

__device__ float g_Wt[HID * HID];                     // Wt[h*128+o] = W[o*128+h]
__device__ float g_anorm[NC * NC];
__device__ __align__(16) __half g_embh[(NQ + 1) * HID];

typedef unsigned long long u64;

static __device__ __forceinline__ u64 pack2(float lo, float hi) {
    u64 r; asm("mov.b64 %0, {%1, %2};" : "=l"(r) : "f"(lo), "f"(hi)); return r;
}
static __device__ __forceinline__ void ffma2(u64 &d, u64 a, u64 b) {
    asm("fma.rn.f32x2 %0, %1, %2, %0;" : "+l"(d) : "l"(a), "l"(b));
}
static __device__ __forceinline__ u64 fadd2(u64 a, u64 b) {
    u64 r; asm("add.rn.f32x2 %0, %1, %2;" : "=l"(r) : "l"(a), "l"(b)); return r;
}
static __device__ __forceinline__ float2 unpack2(u64 v) {
    float x, y; asm("mov.b64 {%0, %1}, %2;" : "=f"(x), "=f"(y) : "l"(v));
    return make_float2(x, y);
}

// ---------------- prep: transpose W, normalized adjacency, fp16 table ----------------
__global__ void prep_kernel(const float* __restrict__ adj,
                            const float* __restrict__ W,
                            const float* __restrict__ qemb) {
    int t = threadIdx.x, b = blockIdx.x;
    if (b < 64) {
        int idx = b * 256 + t;               // 0..16383
        int o = idx >> 7, h = idx & 127;
        g_Wt[h * HID + o] = W[idx];
    } else if (b == 64) {
        int i = t >> 4, j = t & 15;
        float di = 0.f, dj = 0.f;
#pragma unroll
        for (int r = 0; r < NC; r++) { di += adj[r * NC + i]; dj += adj[r * NC + j]; }
        di = di > 0.f ? rsqrtf(di) : 0.f;
        dj = dj > 0.f ? rsqrtf(dj) : 0.f;
        g_anorm[t] = adj[t] * di * dj;
    } else {
        int idx = (b - 65) * 256 + t;        // convert table to fp16
        if (idx < (NQ + 1) * HID) g_embh[idx] = __float2half(qemb[idx]);
    }
}

// ---------------- fused: bucket -> fp16 maxpool -> transpose -> split GEMM -> mix ----------------
__global__ void __launch_bounds__(128)
enc_kernel(const int*   __restrict__ la,
           const float* __restrict__ bias,
           float*       __restrict__ out)
{
    __shared__ __align__(16) float s_ceT[HID * CTS];          // 10240 B, ceT[h][j]
    __shared__ __align__(16) float s_an[NC * NC];             // 1024 B
    __shared__ __align__(16) unsigned char s_u[16 * HID * 8]; // 16384 B union region

    int*            s_assign = (int*)s_u;                          // [0,2048)
    unsigned short* s_buf    = (unsigned short*)(s_u + 2048);      // [2048,4096)
    int*            s_cnt    = (int*)(s_u + 4096);                 // 16 ints
    int*            s_ovf    = (int*)(s_u + 4160);
    float*          s_ce     = (float*)(s_u + 4352);               // 16*128 f32 = 8192 B
    u64*            s_all    = (u64*)s_u;                          // reused after GEMM

    const int tid  = threadIdx.x;
    const int lane = tid & 31;
    const int wrp  = tid >> 5;
    const int b    = blockIdx.x;

    if (tid < NC) s_cnt[tid] = 0;
    if (tid == NC) *s_ovf = 0;
    s_an[tid]       = g_anorm[tid];
    s_an[tid + 128] = g_anorm[tid + 128];

    int4 aa = ((const int4*)(la + (size_t)b * NQ))[tid];
    ((int4*)s_assign)[tid] = aa;
    __syncthreads();

    // ---- bucket (order-free: max over <=64 entries is commutative-exact) ----
    {
        int q0 = tid * 4, c, p;
        c = aa.x; p = atomicAdd(&s_cnt[c], 1); if (p < CS) s_buf[c * CS + p] = (unsigned short)(q0 + 0); else *s_ovf = 1;
        c = aa.y; p = atomicAdd(&s_cnt[c], 1); if (p < CS) s_buf[c * CS + p] = (unsigned short)(q0 + 1); else *s_ovf = 1;
        c = aa.z; p = atomicAdd(&s_cnt[c], 1); if (p < CS) s_buf[c * CS + p] = (unsigned short)(q0 + 2); else *s_ovf = 1;
        c = aa.w; p = atomicAdd(&s_cnt[c], 1); if (p < CS) s_buf[c * CS + p] = (unsigned short)(q0 + 3); else *s_ovf = 1;
    }
    __syncthreads();

    if (*s_ovf) {   // rare order-dependent drop case: serial redo
        if (tid == 0) {
            int cnt[NC];
#pragma unroll
            for (int c = 0; c < NC; c++) cnt[c] = 0;
            for (int q = 0; q < NQ; q++) {
                int c = s_assign[q], p = cnt[c];
                if (p < CS) s_buf[c * CS + p] = (unsigned short)q;
                cnt[c] = p + 1;
            }
#pragma unroll
            for (int c = 0; c < NC; c++) s_cnt[c] = cnt[c];
        }
        __syncthreads();
    }

    // ---- fp16 max-pool: warp w owns cores 4w..4w+3; lane owns h=4*lane..+3 ----
    {
        const uint2* qe2 = (const uint2*)g_embh;   // 32 uint2 per 128-half row
#pragma unroll
        for (int cc = 0; cc < 4; cc++) {
            int c   = wrp * 4 + cc;
            int cnt = s_cnt[c];
            int n   = cnt < CS ? cnt : CS;
            __half hini = (cnt >= CS) ? __ushort_as_half((unsigned short)0xFC00) : __ushort_as_half(0);
            __half2 acc0 = __half2half2(hini), acc1 = acc0;
            int base = c * CS, i = 0;
            for (; i + 4 <= n; i += 4) {
                u64 qq = *(const u64*)&s_buf[base + i];
                int q0 = (int)(qq & 0xFFFFu);
                int q1 = (int)((qq >> 16) & 0xFFFFu);
                int q2 = (int)((qq >> 32) & 0xFFFFu);
                int q3 = (int)((qq >> 48) & 0xFFFFu);
                uint2 u0 = qe2[q0 * 32 + lane];
                uint2 u1 = qe2[q1 * 32 + lane];
                uint2 u2 = qe2[q2 * 32 + lane];
                uint2 u3 = qe2[q3 * 32 + lane];
                acc0 = __hmax2(acc0, *(__half2*)&u0.x); acc1 = __hmax2(acc1, *(__half2*)&u0.y);
                acc0 = __hmax2(acc0, *(__half2*)&u1.x); acc1 = __hmax2(acc1, *(__half2*)&u1.y);
                acc0 = __hmax2(acc0, *(__half2*)&u2.x); acc1 = __hmax2(acc1, *(__half2*)&u2.y);
                acc0 = __hmax2(acc0, *(__half2*)&u3.x); acc1 = __hmax2(acc1, *(__half2*)&u3.y);
            }
            for (; i < n; i++) {
                int q = s_buf[base + i];
                uint2 u0 = qe2[q * 32 + lane];
                acc0 = __hmax2(acc0, *(__half2*)&u0.x); acc1 = __hmax2(acc1, *(__half2*)&u0.y);
            }
            float4 f;
            f.x = __low2float(acc0); f.y = __high2float(acc0);
            f.z = __low2float(acc1); f.w = __high2float(acc1);
            ((float4*)(s_ce + c * HID))[lane] = f;
        }
    }
    __syncthreads();

    // ---- transpose ce[c][h] -> ceT[h][j] (thread owns column h = tid) ----
    {
        float v[16];
#pragma unroll
        for (int j = 0; j < NC; j++) v[j] = s_ce[j * HID + tid];
        float2* row = (float2*)(s_ceT + tid * CTS);
#pragma unroll
        for (int k = 0; k < 8; k++) row[k] = make_float2(v[2 * k], v[2 * k + 1]);
    }
    __syncthreads();

    // ---- split GEMM: hmat[j][o] = sum_h ceT[h][j]*Wt[h][o]; thread (hh,oo): o in {oo,oo+64}, h-half hh ----
    const int hh = tid >> 6, oo = tid & 63;
    u64 a1[8], a2[8];
#pragma unroll
    for (int k = 0; k < 8; k++) { a1[k] = 0ull; a2[k] = 0ull; }
    {
        const float* wp  = g_Wt + hh * 64 * HID;
        const u64*   cer = (const u64*)s_ceT + hh * 64 * (CTS / 2);
#pragma unroll 8
        for (int h0 = 0; h0 < 64; h0++) {
            float w1 = wp[h0 * HID + oo];
            float w2 = wp[h0 * HID + oo + 64];
            u64 w1p = pack2(w1, w1);
            u64 w2p = pack2(w2, w2);
            const u64* row = cer + h0 * (CTS / 2);
            u64 c0 = row[0], c1 = row[1], c2 = row[2], c3 = row[3];
            u64 c4 = row[4], c5 = row[5], c6 = row[6], c7 = row[7];
            ffma2(a1[0], c0, w1p); ffma2(a2[0], c0, w2p);
            ffma2(a1[1], c1, w1p); ffma2(a2[1], c1, w2p);
            ffma2(a1[2], c2, w1p); ffma2(a2[2], c2, w2p);
            ffma2(a1[3], c3, w1p); ffma2(a2[3], c3, w2p);
            ffma2(a1[4], c4, w1p); ffma2(a2[4], c4, w2p);
            ffma2(a1[5], c5, w1p); ffma2(a2[5], c5, w2p);
            ffma2(a1[6], c6, w1p); ffma2(a2[6], c6, w2p);
            ffma2(a1[7], c7, w1p); ffma2(a2[7], c7, w2p);
        }
    }

    // ---- all-gather across h-halves (k-major, conflict-free) ----
    __syncthreads();   // s_u regions (assign/buf/ce) dead; safe to reuse as s_all
#pragma unroll
    for (int k = 0; k < 8; k++) s_all[k * HID + tid]       = a1[k];
#pragma unroll
    for (int k = 0; k < 8; k++) s_all[(k + 8) * HID + tid] = a2[k];
    __syncthreads();
    {
        int p = tid ^ 64;
#pragma unroll
        for (int k = 0; k < 8; k++) a1[k] = fadd2(a1[k], s_all[k * HID + p]);
#pragma unroll
        for (int k = 0; k < 8; k++) a2[k] = fadd2(a2[k], s_all[(k + 8) * HID + p]);
    }

    // ---- mix epilogue: out[i][o] = sum_j anorm[i][j]*hmat[j][o] + bias[o]; thread does 8 i x 2 o ----
    {
        float b1 = bias[oo], b2 = bias[oo + 64];
        float* ob = out + (size_t)b * (NC * HID);
        const u64* an = (const u64*)s_an;
        int ibase = hh * 8;
#pragma unroll
        for (int ii = 0; ii < 8; ii++) {
            int i = ibase + ii;
            const u64* ar = an + i * 8;
            u64 s1 = 0ull, s2 = 0ull;
#pragma unroll
            for (int jp = 0; jp < 8; jp++) {
                u64 av = ar[jp];
                ffma2(s1, av, a1[jp]);
                ffma2(s2, av, a2[jp]);
            }
            float2 f1 = unpack2(s1), f2 = unpack2(s2);
            ob[i * HID + oo]      = f1.x + f1.y + b1;
            ob[i * HID + oo + 64] = f2.x + f2.y + b2;
        }
    }
}

extern "C" void kernel_launch(void* const* d_in, const int* in_sizes, int n_in,
                              void* d_out, int out_size) {
    const int*   la   = (const int*)  d_in[0];   // (2048, 512) int32
    const float* adj  = (const float*)d_in[1];   // (16, 16) f32
    const float* qemb = (const float*)d_in[2];   // (513, 128) f32
    const float* W    = (const float*)d_in[3];   // (128, 128) f32
    const float* bias = (const float*)d_in[4];   // (128,) f32
    float* out = (float*)d_out;                  // (2048, 16, 128) f32

    prep_kernel<<<322, 256>>>(adj, W, qemb);
    enc_kernel<<<NB, 128>>>(la, bias, out);
}

// round 4
// speedup vs baseline: 1.4266x; 1.0416x over previous
#include <cuda_runtime.h>
#include <cuda_fp16.h>
#include <math.h>

#define NQ   512
#define NC   16
#define CS   64
#define HID  128
#define NB   2048
#define CTS  20   // ceT row stride (floats): 16B-aligned rows, 16 data + 4 pad

__device__ float g_Wt[HID * HID];                     // Wt[h*128+o] = W[o*128+h]
__device__ float g_anorm[NC * NC];
__device__ __align__(16) __half g_embh[(NQ + 1) * HID];

typedef unsigned long long u64;

static __device__ __forceinline__ u64 pack2(float lo, float hi) {
    u64 r; asm("mov.b64 %0, {%1, %2};" : "=l"(r) : "f"(lo), "f"(hi)); return r;
}
static __device__ __forceinline__ void ffma2(u64 &d, u64 a, u64 b) {
    asm("fma.rn.f32x2 %0, %1, %2, %0;" : "+l"(d) : "l"(a), "l"(b));
}
static __device__ __forceinline__ u64 fadd2(u64 a, u64 b) {
    u64 r; asm("add.rn.f32x2 %0, %1, %2;" : "=l"(r) : "l"(a), "l"(b)); return r;
}
static __device__ __forceinline__ float2 unpack2(u64 v) {
    float x, y; asm("mov.b64 {%0, %1}, %2;" : "=f"(x), "=f"(y) : "l"(v));
    return make_float2(x, y);
}

// ---------------- prep: transpose W, normalized adjacency, fp16 table ----------------
__global__ void prep_kernel(const float* __restrict__ adj,
                            const float* __restrict__ W,
                            const float* __restrict__ qemb) {
    int t = threadIdx.x, b = blockIdx.x;
    if (b < 64) {
        int idx = b * 256 + t;               // 0..16383
        int o = idx >> 7, h = idx & 127;
        g_Wt[h * HID + o] = W[idx];
    } else if (b == 64) {
        int i = t >> 4, j = t & 15;
        float di = 0.f, dj = 0.f;
#pragma unroll
        for (int r = 0; r < NC; r++) { di += adj[r * NC + i]; dj += adj[r * NC + j]; }
        di = di > 0.f ? rsqrtf(di) : 0.f;
        dj = dj > 0.f ? rsqrtf(dj) : 0.f;
        g_anorm[t] = adj[t] * di * dj;
    } else {
        int idx = (b - 65) * 256 + t;        // convert table to fp16
        if (idx < (NQ + 1) * HID) g_embh[idx] = __float2half(qemb[idx]);
    }
}

// ---------------- fused: bucket -> fp16 maxpool -> transpose -> split GEMM -> mix ----------------
__global__ void __launch_bounds__(128)
enc_kernel(const int*   __restrict__ la,
           const float* __restrict__ bias,
           float*       __restrict__ out)
{
    __shared__ __align__(16) float s_ceT[HID * CTS];          // 10240 B, ceT[h][j]
    __shared__ __align__(16) float s_an[NC * NC];             // 1024 B
    __shared__ __align__(16) unsigned char s_u[16 * HID * 8]; // 16384 B union region

    int*            s_assign = (int*)s_u;                          // [0,2048)
    unsigned short* s_buf    = (unsigned short*)(s_u + 2048);      // [2048,4096)
    int*            s_cnt    = (int*)(s_u + 4096);                 // 16 ints
    int*            s_ovf    = (int*)(s_u + 4160);
    float*          s_ce     = (float*)(s_u + 4352);               // 16*128 f32 = 8192 B
    u64*            s_all    = (u64*)s_u;                          // reused after GEMM

    const int tid  = threadIdx.x;
    const int lane = tid & 31;
    const int wrp  = tid >> 5;
    const int b    = blockIdx.x;

    if (tid < NC) s_cnt[tid] = 0;
    if (tid == NC) *s_ovf = 0;
    s_an[tid]       = g_anorm[tid];
    s_an[tid + 128] = g_anorm[tid + 128];

    int4 aa = ((const int4*)(la + (size_t)b * NQ))[tid];
    ((int4*)s_assign)[tid] = aa;
    __syncthreads();

    // ---- bucket (order-free: max over <=64 entries is commutative-exact) ----
    {
        int q0 = tid * 4, c, p;
        c = aa.x; p = atomicAdd(&s_cnt[c], 1); if (p < CS) s_buf[c * CS + p] = (unsigned short)(q0 + 0); else *s_ovf = 1;
        c = aa.y; p = atomicAdd(&s_cnt[c], 1); if (p < CS) s_buf[c * CS + p] = (unsigned short)(q0 + 1); else *s_ovf = 1;
        c = aa.z; p = atomicAdd(&s_cnt[c], 1); if (p < CS) s_buf[c * CS + p] = (unsigned short)(q0 + 2); else *s_ovf = 1;
        c = aa.w; p = atomicAdd(&s_cnt[c], 1); if (p < CS) s_buf[c * CS + p] = (unsigned short)(q0 + 3); else *s_ovf = 1;
    }
    __syncthreads();

    if (*s_ovf) {   // rare order-dependent drop case: serial redo
        if (tid == 0) {
            int cnt[NC];
#pragma unroll
            for (int c = 0; c < NC; c++) cnt[c] = 0;
            for (int q = 0; q < NQ; q++) {
                int c = s_assign[q], p = cnt[c];
                if (p < CS) s_buf[c * CS + p] = (unsigned short)q;
                cnt[c] = p + 1;
            }
#pragma unroll
            for (int c = 0; c < NC; c++) s_cnt[c] = cnt[c];
        }
        __syncthreads();
    }

    // ---- fp16 max-pool: warp w owns cores 4w..4w+3; lane owns h=4*lane..+3 ----
    {
        const uint2* qe2 = (const uint2*)g_embh;   // 32 uint2 per 128-half row
#pragma unroll
        for (int cc = 0; cc < 4; cc++) {
            int c   = wrp * 4 + cc;
            int cnt = s_cnt[c];
            int n   = cnt < CS ? cnt : CS;
            __half hini = (cnt >= CS) ? __ushort_as_half((unsigned short)0xFC00) : __ushort_as_half(0);
            __half2 acc0 = __half2half2(hini), acc1 = acc0;
            int base = c * CS, i = 0;
            for (; i + 4 <= n; i += 4) {
                u64 qq = *(const u64*)&s_buf[base + i];
                int q0 = (int)(qq & 0xFFFFu);
                int q1 = (int)((qq >> 16) & 0xFFFFu);
                int q2 = (int)((qq >> 32) & 0xFFFFu);
                int q3 = (int)((qq >> 48) & 0xFFFFu);
                uint2 u0 = qe2[q0 * 32 + lane];
                uint2 u1 = qe2[q1 * 32 + lane];
                uint2 u2 = qe2[q2 * 32 + lane];
                uint2 u3 = qe2[q3 * 32 + lane];
                acc0 = __hmax2(acc0, *(__half2*)&u0.x); acc1 = __hmax2(acc1, *(__half2*)&u0.y);
                acc0 = __hmax2(acc0, *(__half2*)&u1.x); acc1 = __hmax2(acc1, *(__half2*)&u1.y);
                acc0 = __hmax2(acc0, *(__half2*)&u2.x); acc1 = __hmax2(acc1, *(__half2*)&u2.y);
                acc0 = __hmax2(acc0, *(__half2*)&u3.x); acc1 = __hmax2(acc1, *(__half2*)&u3.y);
            }
            for (; i < n; i++) {
                int q = s_buf[base + i];
                uint2 u0 = qe2[q * 32 + lane];
                acc0 = __hmax2(acc0, *(__half2*)&u0.x); acc1 = __hmax2(acc1, *(__half2*)&u0.y);
            }
            float4 f;
            f.x = __low2float(acc0); f.y = __high2float(acc0);
            f.z = __low2float(acc1); f.w = __high2float(acc1);
            ((float4*)(s_ce + c * HID))[lane] = f;
        }
    }
    __syncthreads();

    // ---- transpose ce[c][h] -> ceT[h][j] (thread owns column h = tid) ----
    {
        float v[16];
#pragma unroll
        for (int j = 0; j < NC; j++) v[j] = s_ce[j * HID + tid];
        float2* row = (float2*)(s_ceT + tid * CTS);
#pragma unroll
        for (int k = 0; k < 8; k++) row[k] = make_float2(v[2 * k], v[2 * k + 1]);
    }
    __syncthreads();

    // ---- split GEMM: hmat[j][o] = sum_h ceT[h][j]*Wt[h][o]; thread (hh,oo): o in {oo,oo+64}, h-half hh ----
    const int hh = tid >> 6, oo = tid & 63;
    u64 a1[8], a2[8];
#pragma unroll
    for (int k = 0; k < 8; k++) { a1[k] = 0ull; a2[k] = 0ull; }
    {
        const float* wp  = g_Wt + hh * 64 * HID;
        const u64*   cer = (const u64*)s_ceT + hh * 64 * (CTS / 2);
#pragma unroll 8
        for (int h0 = 0; h0 < 64; h0++) {
            float w1 = wp[h0 * HID + oo];
            float w2 = wp[h0 * HID + oo + 64];
            u64 w1p = pack2(w1, w1);
            u64 w2p = pack2(w2, w2);
            const u64* row = cer + h0 * (CTS / 2);
            u64 c0 = row[0], c1 = row[1], c2 = row[2], c3 = row[3];
            u64 c4 = row[4], c5 = row[5], c6 = row[6], c7 = row[7];
            ffma2(a1[0], c0, w1p); ffma2(a2[0], c0, w2p);
            ffma2(a1[1], c1, w1p); ffma2(a2[1], c1, w2p);
            ffma2(a1[2], c2, w1p); ffma2(a2[2], c2, w2p);
            ffma2(a1[3], c3, w1p); ffma2(a2[3], c3, w2p);
            ffma2(a1[4], c4, w1p); ffma2(a2[4], c4, w2p);
            ffma2(a1[5], c5, w1p); ffma2(a2[5], c5, w2p);
            ffma2(a1[6], c6, w1p); ffma2(a2[6], c6, w2p);
            ffma2(a1[7], c7, w1p); ffma2(a2[7], c7, w2p);
        }
    }

    // ---- all-gather across h-halves (k-major, conflict-free) ----
    __syncthreads();   // s_u regions (assign/buf/ce) dead; safe to reuse as s_all
#pragma unroll
    for (int k = 0; k < 8; k++) s_all[k * HID + tid]       = a1[k];
#pragma unroll
    for (int k = 0; k < 8; k++) s_all[(k + 8) * HID + tid] = a2[k];
    __syncthreads();
    {
        int p = tid ^ 64;
#pragma unroll
        for (int k = 0; k < 8; k++) a1[k] = fadd2(a1[k], s_all[k * HID + p]);
#pragma unroll
        for (int k = 0; k < 8; k++) a2[k] = fadd2(a2[k], s_all[(k + 8) * HID + p]);
    }

    // ---- mix epilogue: out[i][o] = sum_j anorm[i][j]*hmat[j][o] + bias[o]; thread does 8 i x 2 o ----
    {
        float b1 = bias[oo], b2 = bias[oo + 64];
        float* ob = out + (size_t)b * (NC * HID);
        const u64* an = (const u64*)s_an;
        int ibase = hh * 8;
#pragma unroll
        for (int ii = 0; ii < 8; ii++) {
            int i = ibase + ii;
            const u64* ar = an + i * 8;
            u64 s1 = 0ull, s2 = 0ull;
#pragma unroll
            for (int jp = 0; jp < 8; jp++) {
                u64 av = ar[jp];
                ffma2(s1, av, a1[jp]);
                ffma2(s2, av, a2[jp]);
            }
            float2 f1 = unpack2(s1), f2 = unpack2(s2);
            ob[i * HID + oo]      = f1.x + f1.y + b1;
            ob[i * HID + oo + 64] = f2.x + f2.y + b2;
        }
    }
}

extern "C" void kernel_launch(void* const* d_in, const int* in_sizes, int n_in,
                              void* d_out, int out_size) {
    const int*   la   = (const int*)  d_in[0];   // (2048, 512) int32
    const float* adj  = (const float*)d_in[1];   // (16, 16) f32
    const float* qemb = (const float*)d_in[2];   // (513, 128) f32
    const float* W    = (const float*)d_in[3];   // (128, 128) f32
    const float* bias = (const float*)d_in[4];   // (128,) f32
    float* out = (float*)d_out;                  // (2048, 16, 128) f32

    prep_kernel<<<322, 256>>>(adj, W, qemb);
    enc_kernel<<<NB, 128>>>(la, bias, out);
}

// round 6
// speedup vs baseline: 1.9145x; 1.3420x over previous
#include <cuda_runtime.h>
#include <cuda_fp16.h>
#include <math.h>
#include <stdint.h>

#define NQ   512
#define NC   16
#define CS   64
#define HID  128
#define NB   2048
#define BPBLK  16
#define BPR    4          // batches per round
#define ROUNDS 4
#define GRID   (NB / BPBLK)   // 128
#define THREADS 512

#define WST  272          // padded fp16 row stride in bytes (128 halfs + 8 pad)

// ---- smem offsets ----
#define OFF_TAB  0                          // 512*256   = 131072
#define OFF_W    131072                     // 128*272   = 34816
#define OFF_M    165888                     // 64*272    = 17408
#define OFF_BUF  183296                     // 4*16*64*2 = 8192
#define OFF_CE   191488                     // 4*16*32*8 = 16384
#define OFF_AN2  207872                     // 256*8     = 2048
#define OFF_BIAS 209920                     // 512
#define OFF_CNT  210432                     // 64*4      = 256
#define OFF_OVF  210688                     // 16
#define SMEM_REQ 210944

__device__ float g_anorm[NC * NC];
__device__ __align__(16) __half g_embh[(NQ + 1) * HID];
__device__ __align__(16) __half g_Wh[HID * HID];   // W[o][h], fp16

typedef unsigned long long u64;

static __device__ __forceinline__ uint32_t smem_u32(const void* p) {
    uint32_t a;
    asm("{ .reg .u64 t; cvta.to.shared.u64 t, %1; cvt.u32.u64 %0, t; }" : "=r"(a) : "l"(p));
    return a;
}
static __device__ __forceinline__ u64 pack2(float lo, float hi) {
    u64 r; asm("mov.b64 %0, {%1, %2};" : "=l"(r) : "f"(lo), "f"(hi)); return r;
}
static __device__ __forceinline__ void ffma2(u64 &d, u64 a, u64 b) {
    asm("fma.rn.f32x2 %0, %1, %2, %0;" : "+l"(d) : "l"(a), "l"(b));
}
static __device__ __forceinline__ float2 unpack2(u64 v) {
    float x, y; asm("mov.b64 {%0, %1}, %2;" : "=f"(x), "=f"(y) : "l"(v));
    return make_float2(x, y);
}
static __device__ __forceinline__ void ldsm_x4(uint32_t* r, uint32_t addr) {
    asm volatile("ldmatrix.sync.aligned.m8n8.x4.shared.b16 {%0,%1,%2,%3}, [%4];"
        : "=r"(r[0]), "=r"(r[1]), "=r"(r[2]), "=r"(r[3]) : "r"(addr));
}
static __device__ __forceinline__ void mma16816(float* d, const uint32_t* a, const uint32_t* b) {
    asm volatile("mma.sync.aligned.m16n8k16.row.col.f32.f16.f16.f32 "
        "{%0,%1,%2,%3}, {%4,%5,%6,%7}, {%8,%9}, {%0,%1,%2,%3};"
        : "+f"(d[0]), "+f"(d[1]), "+f"(d[2]), "+f"(d[3])
        : "r"(a[0]), "r"(a[1]), "r"(a[2]), "r"(a[3]), "r"(b[0]), "r"(b[1]));
}

// ---------------- prep: anorm, fp16 table, fp16 W ----------------
__global__ void prep_kernel(const float* __restrict__ adj,
                            const float* __restrict__ W,
                            const float* __restrict__ qemb) {
    int t = threadIdx.x, b = blockIdx.x;
    if (b < 64) {
        int idx = b * 256 + t;                 // 16384 W entries
        g_Wh[idx] = __float2half(W[idx]);
    } else if (b == 64) {
        int i = t >> 4, j = t & 15;
        float di = 0.f, dj = 0.f;
#pragma unroll
        for (int r = 0; r < NC; r++) { di += adj[r * NC + i]; dj += adj[r * NC + j]; }
        di = di > 0.f ? rsqrtf(di) : 0.f;
        dj = dj > 0.f ? rsqrtf(dj) : 0.f;
        g_anorm[t] = adj[t] * di * dj;
    } else {
        int idx = (b - 65) * 256 + t;
        if (idx < (NQ + 1) * HID) g_embh[idx] = __float2half(qemb[idx]);
    }
}

// ---------------- fused: smem table -> bucket -> pool -> mix -> mma.sync GEMM ----------------
__global__ void __launch_bounds__(THREADS, 1)
enc_kernel(const int*   __restrict__ la,
           const float* __restrict__ bias,
           float*       __restrict__ out)
{
    extern __shared__ __align__(16) char smem[];
    const uint32_t sb = smem_u32(smem);

    const int tid  = threadIdx.x;
    const int lane = tid & 31;
    const int w    = tid >> 5;
    const int bb0  = blockIdx.x * BPBLK;

    unsigned short* s_buf  = (unsigned short*)(smem + OFF_BUF);
    int*            s_cnt  = (int*)(smem + OFF_CNT);
    int*            s_ovf  = (int*)(smem + OFF_OVF);
    u64*            s_an2  = (u64*)(smem + OFF_AN2);
    float*          s_bias = (float*)(smem + OFF_BIAS);

    // ---- phase 0: constants + table + W into smem ----
    if (tid < 256) { float a = g_anorm[tid]; s_an2[tid] = pack2(a, a); }
    else if (tid < 384) s_bias[tid - 256] = bias[tid - 256];
    {
        const uint4* src = (const uint4*)g_embh;
        uint4* dst = (uint4*)(smem + OFF_TAB);
#pragma unroll
        for (int i = 0; i < 16; i++) dst[i * THREADS + tid] = src[i * THREADS + tid];
    }
    {
        const uint4* src = (const uint4*)g_Wh;
#pragma unroll
        for (int k = 0; k < 4; k++) {
            int idx = k * THREADS + tid;          // 2048 uint4
            int o = idx >> 4, seg = idx & 15;
            *(uint4*)(smem + OFF_W + o * WST + seg * 16) = src[idx];
        }
    }
    __syncthreads();

    for (int R = 0; R < ROUNDS; R++) {
        // ---- zero counters ----
        if (tid < BPR * NC) s_cnt[tid] = 0;
        if (tid < BPR) s_ovf[tid] = 0;
        __syncthreads();

        // ---- bucket: warps 0..3, one batch each ----
        if (w < BPR) {
            const int batch = bb0 + R * BPR + w;
            const int4* ap = (const int4*)(la + (size_t)batch * NQ);
            const int cb = w * NC;
#pragma unroll
            for (int it = 0; it < 4; it++) {
                int4 v = ap[it * 32 + lane];
                int q0 = (it * 32 + lane) * 4;
                int p;
                p = atomicAdd(&s_cnt[cb + v.x], 1); if (p < CS) s_buf[(cb + v.x) * CS + p] = (unsigned short)(q0 + 0); else s_ovf[w] = 1;
                p = atomicAdd(&s_cnt[cb + v.y], 1); if (p < CS) s_buf[(cb + v.y) * CS + p] = (unsigned short)(q0 + 1); else s_ovf[w] = 1;
                p = atomicAdd(&s_cnt[cb + v.z], 1); if (p < CS) s_buf[(cb + v.z) * CS + p] = (unsigned short)(q0 + 2); else s_ovf[w] = 1;
                p = atomicAdd(&s_cnt[cb + v.w], 1); if (p < CS) s_buf[(cb + v.w) * CS + p] = (unsigned short)(q0 + 3); else s_ovf[w] = 1;
            }
        }
        __syncthreads();

        // ---- rare overflow fallback: serial, qubit-order-correct ----
        if (tid < BPR && s_ovf[tid]) {
            const int batch = bb0 + R * BPR + tid;
            int cnt[NC];
#pragma unroll
            for (int c = 0; c < NC; c++) cnt[c] = 0;
            for (int q = 0; q < NQ; q++) {
                int c = la[(size_t)batch * NQ + q];
                int p = cnt[c];
                if (p < CS) s_buf[(tid * NC + c) * CS + p] = (unsigned short)q;
                cnt[c] = p + 1;
            }
#pragma unroll
            for (int c = 0; c < NC; c++) s_cnt[tid * NC + c] = cnt[c];
        }
        __syncthreads();

        // ---- pool from smem table: warp -> (batch w>>2, cores (w&3)*4..+3) ----
        {
            const int bb = w >> 2;
            const int c0 = (w & 3) * 4;
            uint2* ce = (uint2*)(smem + OFF_CE);
#pragma unroll
            for (int cc = 0; cc < 4; cc++) {
                int c = c0 + cc;
                int cnt = s_cnt[bb * NC + c];
                int n = cnt < CS ? cnt : CS;
                __half2 a0 = __half2half2(__ushort_as_half(
                                 (unsigned short)(cnt >= CS ? 0xFC00 : 0)));
                __half2 a1 = a0;
                const unsigned short* bq = &s_buf[(bb * NC + c) * CS];
                int i = 0;
                for (; i + 4 <= n; i += 4) {
                    u64 qq = *(const u64*)(bq + i);
                    uint32_t q0 = (uint32_t)(qq) & 0xFFFFu;
                    uint32_t q1 = (uint32_t)(qq >> 16) & 0xFFFFu;
                    uint32_t q2 = (uint32_t)(qq >> 32) & 0xFFFFu;
                    uint32_t q3 = (uint32_t)(qq >> 48) & 0xFFFFu;
                    uint2 r0 = *(const uint2*)(smem + OFF_TAB + q0 * 256u + lane * 8u);
                    uint2 r1 = *(const uint2*)(smem + OFF_TAB + q1 * 256u + lane * 8u);
                    uint2 r2 = *(const uint2*)(smem + OFF_TAB + q2 * 256u + lane * 8u);
                    uint2 r3 = *(const uint2*)(smem + OFF_TAB + q3 * 256u + lane * 8u);
                    a0 = __hmax2(a0, *(__half2*)&r0.x); a1 = __hmax2(a1, *(__half2*)&r0.y);
                    a0 = __hmax2(a0, *(__half2*)&r1.x); a1 = __hmax2(a1, *(__half2*)&r1.y);
                    a0 = __hmax2(a0, *(__half2*)&r2.x); a1 = __hmax2(a1, *(__half2*)&r2.y);
                    a0 = __hmax2(a0, *(__half2*)&r3.x); a1 = __hmax2(a1, *(__half2*)&r3.y);
                }
                for (; i < n; i++) {
                    uint32_t q = bq[i];
                    uint2 r0 = *(const uint2*)(smem + OFF_TAB + q * 256u + lane * 8u);
                    a0 = __hmax2(a0, *(__half2*)&r0.x); a1 = __hmax2(a1, *(__half2*)&r0.y);
                }
                uint2 st;
                st.x = *(uint32_t*)&a0; st.y = *(uint32_t*)&a1;
                ce[(bb * NC + c) * 32 + lane] = st;
            }
        }
        __syncthreads();

        // ---- mix: warp -> (batch w>>2, i-group w&3); lane owns 4 h-cols ----
        {
            const int bb = w >> 2, ig = w & 3;
            const uint2* cep = (const uint2*)(smem + OFF_CE) + (bb * NC) * 32 + lane;
            u64 mlo[4], mhi[4];
#pragma unroll
            for (int ii = 0; ii < 4; ii++) { mlo[ii] = 0ull; mhi[ii] = 0ull; }
#pragma unroll
            for (int j = 0; j < NC; j++) {
                uint2 cu = cep[j * 32];
                float2 flo = __half22float2(*(__half2*)&cu.x);
                float2 fhi = __half22float2(*(__half2*)&cu.y);
                u64 vlo = pack2(flo.x, flo.y);
                u64 vhi = pack2(fhi.x, fhi.y);
#pragma unroll
                for (int ii = 0; ii < 4; ii++) {
                    u64 ap = s_an2[(ig * 4 + ii) * NC + j];
                    ffma2(mlo[ii], vlo, ap);
                    ffma2(mhi[ii], vhi, ap);
                }
            }
#pragma unroll
            for (int ii = 0; ii < 4; ii++) {
                int r = bb * NC + ig * 4 + ii;     // 0..63
                float2 l = unpack2(mlo[ii]);
                float2 h = unpack2(mhi[ii]);
                __half2 h0 = __floats2half2_rn(l.x, l.y);
                __half2 h1 = __floats2half2_rn(h.x, h.y);
                uint2 st; st.x = *(uint32_t*)&h0; st.y = *(uint32_t*)&h1;
                *(uint2*)(smem + OFF_M + r * WST + lane * 8) = st;
            }
        }
        __syncthreads();

        // ---- GEMM: D[64,128] = M[64,128] x W[128,128]^T via mma.sync ----
        {
            const int rt = w & 3;        // row tile = batch in round
            const int ct = w >> 2;       // col tile (32 cols)
            float d[4][4];
#pragma unroll
            for (int nt = 0; nt < 4; nt++)
#pragma unroll
                for (int k = 0; k < 4; k++) d[nt][k] = 0.f;

            const uint32_t aBase = sb + OFF_M
                + (uint32_t)(rt * 16 + (lane & 15)) * WST + (uint32_t)((lane >> 4) * 16);
            const uint32_t bBase0 = sb + OFF_W
                + (uint32_t)(ct * 32 + (lane & 7) + ((lane >> 4) * 8)) * WST
                + (uint32_t)(((lane >> 3) & 1) * 16);
            const uint32_t bBase1 = bBase0 + 16 * WST;

#pragma unroll
            for (int s = 0; s < 8; s++) {
                uint32_t a[4], b0[4], b1[4];
                ldsm_x4(a,  aBase  + s * 32);
                ldsm_x4(b0, bBase0 + s * 32);
                ldsm_x4(b1, bBase1 + s * 32);
                mma16816(d[0], a, b0 + 0);
                mma16816(d[1], a, b0 + 2);
                mma16816(d[2], a, b1 + 0);
                mma16816(d[3], a, b1 + 2);
            }

            // ---- epilogue: bias + direct stores ----
            const int g = lane >> 2, t = lane & 3;
            float* ob = out + (size_t)(bb0 + R * BPR + rt) * (NC * HID);
            float* o0 = ob + g * HID;
            float* o1 = ob + (g + 8) * HID;
#pragma unroll
            for (int nt = 0; nt < 4; nt++) {
                int col = ct * 32 + nt * 8 + 2 * t;
                float bv0 = s_bias[col], bv1 = s_bias[col + 1];
                *(float2*)(o0 + col) = make_float2(d[nt][0] + bv0, d[nt][1] + bv1);
                *(float2*)(o1 + col) = make_float2(d[nt][2] + bv0, d[nt][3] + bv1);
            }
        }
        __syncthreads();
    }
}

extern "C" void kernel_launch(void* const* d_in, const int* in_sizes, int n_in,
                              void* d_out, int out_size) {
    const int*   la   = (const int*)  d_in[0];   // (2048, 512) int32
    const float* adj  = (const float*)d_in[1];   // (16, 16) f32
    const float* qemb = (const float*)d_in[2];   // (513, 128) f32
    const float* W    = (const float*)d_in[3];   // (128, 128) f32
    const float* bias = (const float*)d_in[4];   // (128,) f32
    float* out = (float*)d_out;                  // (2048, 16, 128) f32

    cudaFuncSetAttribute(enc_kernel, cudaFuncAttributeMaxDynamicSharedMemorySize, SMEM_REQ);
    prep_kernel<<<322, 256>>>(adj, W, qemb);
    enc_kernel<<<GRID, THREADS, SMEM_REQ>>>(la, bias, out);
}